// round 6
// baseline (speedup 1.0000x reference)
#include <cuda_runtime.h>
#include <cstdint>
#include <math.h>

#define NN   50000
#define DIN  100
#define DHID 256
#define DOUT 40
#define EE   800000

// ---------------- scratch ----------------
__device__ float g_agg1[(size_t)NN * DIN];
__device__ float g_h1  [(size_t)NN * DHID];
__device__ float g_y2  [(size_t)NN * DOUT];
__device__ float g_agg2[(size_t)NN * DOUT];
__device__ float g_sum1[DHID], g_sq1[DHID];
__device__ float g_sum2[DOUT], g_sq2[DOUT];
__device__ int   g_cnt[NN];      // in-degree
__device__ int   g_rowptr[NN];   // CSR start
__device__ int   g_pos[NN];      // fill cursor
__device__ int   g_eidx[EE];     // src per CSR slot
__device__ int   g_ei64;

// ---------------- helpers ----------------
__device__ __forceinline__ void load_edge(const void* ei, int E, int e, int& s, int& d) {
    if (g_ei64) {
        const long long* p = (const long long*)ei;
        s = (int)p[e]; d = (int)p[E + e];
    } else {
        const int* p = (const int*)ei;
        s = p[e]; d = p[E + e];
    }
}
__device__ __forceinline__ int load_dst(const void* ei, int E, int e) {
    if (g_ei64) return (int)((const long long*)ei)[E + e];
    return ((const int*)ei)[E + e];
}

__device__ __forceinline__ void cp_async16(unsigned dst, const void* src, int src_bytes) {
    asm volatile("cp.async.cg.shared.global [%0], [%1], 16, %2;"
                 :: "r"(dst), "l"(src), "r"(src_bytes));
}
__device__ __forceinline__ void cp_async_commit() {
    asm volatile("cp.async.commit_group;" ::: "memory");
}
template <int N_>
__device__ __forceinline__ void cp_async_wait() {
    asm volatile("cp.async.wait_group %0;" :: "n"(N_) : "memory");
}

// ---------------- init: detect dtype, zero stats + counters ----------------
__global__ void k_init(const int* ei, int N) {
    int t = blockIdx.x * blockDim.x + threadIdx.x;
    if (blockIdx.x == 0) {
        if (threadIdx.x < 32) {
            int v = ei[2 * threadIdx.x + 1];
            unsigned b = __ballot_sync(0xffffffffu, v == 0);
            if (threadIdx.x == 0) g_ei64 = (b == 0xffffffffu) ? 1 : 0;
        }
        if (threadIdx.x < DHID) { g_sum1[threadIdx.x] = 0.f; g_sq1[threadIdx.x] = 0.f; }
        if (threadIdx.x < DOUT) { g_sum2[threadIdx.x] = 0.f; g_sq2[threadIdx.x] = 0.f; }
    }
    for (int i = t; i < N; i += gridDim.x * blockDim.x) g_cnt[i] = 0;
}

// ---------------- CSR build ----------------
__global__ void k_count(const void* __restrict__ ei, int E) {
    int e = blockIdx.x * blockDim.x + threadIdx.x;
    if (e < E) atomicAdd(&g_cnt[load_dst(ei, E, e)], 1);
}

__global__ void k_scan(int N) {
    __shared__ int ps[1024];
    int t = threadIdx.x;
    int chunk = (N + 1023) >> 10;
    int i0 = t * chunk, i1 = min(i0 + chunk, N);
    int s = 0;
    for (int i = i0; i < i1; i++) s += g_cnt[i];
    ps[t] = s;
    __syncthreads();
    for (int off = 1; off < 1024; off <<= 1) {
        int v = (t >= off) ? ps[t - off] : 0;
        __syncthreads();
        ps[t] += v;
        __syncthreads();
    }
    int run = ps[t] - s;   // exclusive prefix
    for (int i = i0; i < i1; i++) {
        g_rowptr[i] = run;
        g_pos[i] = run;
        run += g_cnt[i];
    }
}

__global__ void k_fill(const void* __restrict__ ei, int E) {
    int e = blockIdx.x * blockDim.x + threadIdx.x;
    if (e >= E) return;
    int s, d;
    load_edge(ei, E, e, s, d);
    int slot = atomicAdd(&g_pos[d], 1);
    g_eidx[slot] = s;
}

// ---- gather1: agg1 = x_i + sum_{nbr} x_nbr ; thread = (node, chunk 0..24) ----
__global__ void k_gather1(const float* __restrict__ x, int N) {
    int t = blockIdx.x * blockDim.x + threadIdx.x;
    if (t >= N * 25) return;
    int node = t / 25;
    int ch = t - node * 25;
    float4 v = ((const float4*)x)[t];   // t == node*25 + ch
    int start = g_rowptr[node], cnt = g_cnt[node];
    for (int i = 0; i < cnt; i++) {
        int nbr = __ldg(&g_eidx[start + i]);
        float4 u = ((const float4*)x)[nbr * 25 + ch];
        v.x += u.x; v.y += u.y; v.z += u.z; v.w += u.w;
    }
    ((float4*)g_agg1)[t] = v;
}

// ---- gemm1: h1 = agg1 @ W1 via tf32 mma, 2-stage K pipeline, fused BN stats ----
#define AS_STRIDE 108
#define BS_STRIDE 136

__global__ void __launch_bounds__(256) k_gemm1_tf32(const float* __restrict__ W1, int M) {
    extern __shared__ unsigned sm[];
    unsigned* As = sm;                      // 128*108
    unsigned* Bs = sm + 128 * AS_STRIDE;    // 104*136

    int tid = threadIdx.x;
    int lane = tid & 31, warp = tid >> 5;
    int warp_m = warp >> 1;
    int warp_n = warp & 1;
    int grp = lane >> 2, qd = lane & 3;
    int row0 = blockIdx.x * 128, col0 = blockIdx.y * 128;

    int m = tid >> 1, h = tid & 1;
    int r = row0 + m;
    bool rv = (r < M);
    unsigned adst = (unsigned)__cvta_generic_to_shared(&As[m * AS_STRIDE]);
    const float* asrc = &g_agg1[(size_t)(rv ? r : 0) * DIN];

    // ---- stage 0: K cols 0..55 (A chunks 0..13, B rows 0..55) ----
#pragma unroll
    for (int c = h * 7; c < h * 7 + 7; c++)
        cp_async16(adst + c * 16, asrc + c * 4, rv ? 16 : 0);
#pragma unroll
    for (int i = 0; i < 7; i++) {            // 56*32 = 1792 = 256*7
        int cid = tid + 256 * i;
        int k = cid >> 5, c4 = (cid & 31) * 4;
        unsigned dst = (unsigned)__cvta_generic_to_shared(&Bs[k * BS_STRIDE + c4]);
        cp_async16(dst, &W1[k * DHID + col0 + c4], 16);
    }
    cp_async_commit();

    // ---- stage 1: K cols 56..103 (A chunks 14..25, B rows 56..103) ----
#pragma unroll
    for (int c = 14 + h * 6; c < 14 + h * 6 + 6; c++) {
        int sz = (rv && c < 25) ? 16 : 0;    // chunk 25 = cols 100..103 -> zero
        cp_async16(adst + c * 16, asrc + c * 4, sz);
    }
#pragma unroll
    for (int i = 0; i < 6; i++) {            // 48*32 = 1536 = 256*6
        int cid = tid + 256 * i;
        int k = 56 + (cid >> 5), c4 = (cid & 31) * 4;
        unsigned dst = (unsigned)__cvta_generic_to_shared(&Bs[k * BS_STRIDE + c4]);
        const float* src = &W1[(k < DIN ? k : 0) * DHID + col0 + c4];
        cp_async16(dst, src, (k < DIN) ? 16 : 0);
    }
    cp_async_commit();

    float acc[2][8][4];
#pragma unroll
    for (int mt = 0; mt < 2; mt++)
#pragma unroll
        for (int nt = 0; nt < 8; nt++)
#pragma unroll
            for (int j = 0; j < 4; j++) acc[mt][nt][j] = 0.f;

    cp_async_wait<1>();
    __syncthreads();

#pragma unroll
    for (int ks = 0; ks < 13; ks++) {
        if (ks == 7) {                       // stage-1 data needed from here
            cp_async_wait<0>();
            __syncthreads();
        }
        int k0 = ks * 8;
        unsigned a[2][4];
#pragma unroll
        for (int mt = 0; mt < 2; mt++) {
            const unsigned* Ar  = &As[(warp_m * 32 + mt * 16 + grp) * AS_STRIDE + k0 + qd];
            const unsigned* Ar8 = Ar + 8 * AS_STRIDE;
            a[mt][0] = Ar[0];  a[mt][1] = Ar8[0];
            a[mt][2] = Ar[4];  a[mt][3] = Ar8[4];
        }
#pragma unroll
        for (int nt = 0; nt < 8; nt++) {
            const unsigned* Bp = &Bs[(k0 + qd) * BS_STRIDE + warp_n * 64 + nt * 8 + grp];
            unsigned b0 = Bp[0];
            unsigned b1 = Bp[4 * BS_STRIDE];
#pragma unroll
            for (int mt = 0; mt < 2; mt++) {
                asm volatile(
                    "mma.sync.aligned.m16n8k8.row.col.f32.tf32.tf32.f32 "
                    "{%0,%1,%2,%3},{%4,%5,%6,%7},{%8,%9},{%0,%1,%2,%3};"
                    : "+f"(acc[mt][nt][0]), "+f"(acc[mt][nt][1]),
                      "+f"(acc[mt][nt][2]), "+f"(acc[mt][nt][3])
                    : "r"(a[mt][0]), "r"(a[mt][1]), "r"(a[mt][2]), "r"(a[mt][3]),
                      "r"(b0), "r"(b1));
            }
        }
    }

#pragma unroll
    for (int nt = 0; nt < 8; nt++) {
        int c = col0 + warp_n * 64 + nt * 8 + 2 * qd;
        float s0 = 0.f, s1 = 0.f, q0 = 0.f, q1 = 0.f;
#pragma unroll
        for (int mt = 0; mt < 2; mt++) {
            int rr = row0 + warp_m * 32 + mt * 16 + grp;
            float d0 = acc[mt][nt][0], d1 = acc[mt][nt][1];
            float d2 = acc[mt][nt][2], d3 = acc[mt][nt][3];
            if (rr < M)     *(float2*)&g_h1[(size_t)rr * DHID + c] = make_float2(d0, d1);
            if (rr + 8 < M) *(float2*)&g_h1[(size_t)(rr + 8) * DHID + c] = make_float2(d2, d3);
            s0 += d0 + d2;  s1 += d1 + d3;
            q0 = fmaf(d0, d0, fmaf(d2, d2, q0));
            q1 = fmaf(d1, d1, fmaf(d3, d3, q1));
        }
#pragma unroll
        for (int o = 4; o < 32; o <<= 1) {
            s0 += __shfl_xor_sync(0xffffffffu, s0, o);
            s1 += __shfl_xor_sync(0xffffffffu, s1, o);
            q0 += __shfl_xor_sync(0xffffffffu, q0, o);
            q1 += __shfl_xor_sync(0xffffffffu, q1, o);
        }
        if (lane < 4) {
            atomicAdd(&g_sum1[c], s0);
            atomicAdd(&g_sum1[c + 1], s1);
            atomicAdd(&g_sq1[c], q0);
            atomicAdd(&g_sq1[c + 1], q1);
        }
    }
}

// ---- gemm2: y2 = relu(BN(h1)) @ W2 via tf32 mma; fin1 fused in prologue ----
#define G2_AST 68
__global__ void __launch_bounds__(256) k_gemm2_tf32(const float* __restrict__ W2,
                                                    const float* __restrict__ gamma1,
                                                    const float* __restrict__ beta1,
                                                    float invN, int M) {
    extern __shared__ unsigned sm2[];
    unsigned* As = sm2;                        // 128*68
    unsigned* Bs = sm2 + 128 * G2_AST;         // 256*40
    float* ssc = (float*)(Bs + 256 * DOUT);    // 256
    float* ssh = ssc + 256;                    // 256

    int tid = threadIdx.x;
    int lane = tid & 31, warp = tid >> 5;
    int grp = lane >> 2, qd = lane & 3;
    int row0 = blockIdx.x * 128;

    {   // fused fin1
        float mean = g_sum1[tid] * invN;
        float var = g_sq1[tid] * invN - mean * mean;
        float sc = gamma1[tid] * rsqrtf(var + 1e-5f);
        ssc[tid] = sc;
        ssh[tid] = beta1[tid] - mean * sc;
    }
#pragma unroll
    for (int i = 0; i < 40; i++) {
        int idx = tid + 256 * i;
        Bs[idx] = __float_as_uint(W2[idx]);
    }
    __syncthreads();

    float acc[5][4];
#pragma unroll
    for (int nt = 0; nt < 5; nt++)
#pragma unroll
        for (int j = 0; j < 4; j++) acc[nt][j] = 0.f;

    for (int st = 0; st < 4; st++) {
        int k0 = st * 64;
        if (st) __syncthreads();
        {
            int m = tid >> 1, h = (tid & 1) * 32;
            int r = row0 + m;
            unsigned* dst = &As[m * G2_AST + h];
            if (r < M) {
                const float4* src = (const float4*)&g_h1[(size_t)r * DHID + k0 + h];
#pragma unroll
                for (int i = 0; i < 8; i++) {
                    float4 v = src[i];
                    int c = k0 + h + i * 4;
                    dst[i * 4 + 0] = __float_as_uint(fmaxf(fmaf(v.x, ssc[c + 0], ssh[c + 0]), 0.f));
                    dst[i * 4 + 1] = __float_as_uint(fmaxf(fmaf(v.y, ssc[c + 1], ssh[c + 1]), 0.f));
                    dst[i * 4 + 2] = __float_as_uint(fmaxf(fmaf(v.z, ssc[c + 2], ssh[c + 2]), 0.f));
                    dst[i * 4 + 3] = __float_as_uint(fmaxf(fmaf(v.w, ssc[c + 3], ssh[c + 3]), 0.f));
                }
            } else {
#pragma unroll
                for (int i = 0; i < 32; i++) dst[i] = 0;
            }
        }
        __syncthreads();
#pragma unroll
        for (int ks = 0; ks < 8; ks++) {
            int kk = ks * 8;
            const unsigned* Ar = &As[(warp * 16 + grp) * G2_AST + kk + qd];
            unsigned a0 = Ar[0], a1 = Ar[8 * G2_AST], a2 = Ar[4], a3 = Ar[8 * G2_AST + 4];
#pragma unroll
            for (int nt = 0; nt < 5; nt++) {
                const unsigned* Bp = &Bs[(k0 + kk + qd) * DOUT + nt * 8 + grp];
                unsigned b0 = Bp[0];
                unsigned b1 = Bp[4 * DOUT];
                asm volatile(
                    "mma.sync.aligned.m16n8k8.row.col.f32.tf32.tf32.f32 "
                    "{%0,%1,%2,%3},{%4,%5,%6,%7},{%8,%9},{%0,%1,%2,%3};"
                    : "+f"(acc[nt][0]), "+f"(acc[nt][1]),
                      "+f"(acc[nt][2]), "+f"(acc[nt][3])
                    : "r"(a0), "r"(a1), "r"(a2), "r"(a3), "r"(b0), "r"(b1));
            }
        }
    }

    int r = row0 + warp * 16 + grp;
#pragma unroll
    for (int nt = 0; nt < 5; nt++) {
        int c = nt * 8 + 2 * qd;
        if (r < M)
            *(float2*)&g_y2[r * DOUT + c] = make_float2(acc[nt][0], acc[nt][1]);
        if (r + 8 < M)
            *(float2*)&g_y2[(r + 8) * DOUT + c] = make_float2(acc[nt][2], acc[nt][3]);
    }
}

// ---- gather2: agg2 = y2_i + sum y2_nbr, fused column stats ----
#define G2BLOCKS 250
__global__ void __launch_bounds__(256) k_gather2(int N) {
    __shared__ float bsum[DOUT], bsq[DOUT];
    int tid = threadIdx.x;
    if (tid < DOUT) { bsum[tid] = 0.f; bsq[tid] = 0.f; }
    __syncthreads();

    int t0 = blockIdx.x * 256 + tid;
    const int stride = G2BLOCKS * 256;      // 64000, multiple of 10
    int ch = t0 % 10;                        // invariant across iterations
    float4 rs = make_float4(0.f, 0.f, 0.f, 0.f);
    float4 rq = make_float4(0.f, 0.f, 0.f, 0.f);

    for (int t = t0; t < N * 10; t += stride) {
        int node = t / 10;
        float4 v = ((const float4*)g_y2)[t];
        int start = g_rowptr[node], cnt = g_cnt[node];
        for (int i = 0; i < cnt; i++) {
            int nbr = __ldg(&g_eidx[start + i]);
            float4 u = ((const float4*)g_y2)[nbr * 10 + ch];
            v.x += u.x; v.y += u.y; v.z += u.z; v.w += u.w;
        }
        ((float4*)g_agg2)[t] = v;
        rs.x += v.x; rs.y += v.y; rs.z += v.z; rs.w += v.w;
        rq.x = fmaf(v.x, v.x, rq.x); rq.y = fmaf(v.y, v.y, rq.y);
        rq.z = fmaf(v.z, v.z, rq.z); rq.w = fmaf(v.w, v.w, rq.w);
    }
    int c = ch * 4;
    atomicAdd(&bsum[c + 0], rs.x); atomicAdd(&bsum[c + 1], rs.y);
    atomicAdd(&bsum[c + 2], rs.z); atomicAdd(&bsum[c + 3], rs.w);
    atomicAdd(&bsq[c + 0], rq.x);  atomicAdd(&bsq[c + 1], rq.y);
    atomicAdd(&bsq[c + 2], rq.z);  atomicAdd(&bsq[c + 3], rq.w);
    __syncthreads();
    if (tid < DOUT) {
        atomicAdd(&g_sum2[tid], bsum[tid]);
        atomicAdd(&g_sq2[tid], bsq[tid]);
    }
}

// ---- fin2 fused into log_softmax ----
__global__ void k_logsoftmax(float* __restrict__ out,
                             const float* __restrict__ gamma2,
                             const float* __restrict__ beta2,
                             float invN, int M) {
    __shared__ float sc2[DOUT], sh2[DOUT];
    int t = threadIdx.x;
    if (t < DOUT) {
        float mean = g_sum2[t] * invN;
        float var = g_sq2[t] * invN - mean * mean;
        float sc = gamma2[t] * rsqrtf(var + 1e-5f);
        sc2[t] = sc;
        sh2[t] = beta2[t] - mean * sc;
    }
    __syncthreads();
    int w = (blockIdx.x * blockDim.x + t) >> 5;
    int l = t & 31;
    if (w >= M) return;
    const float* a = &g_agg2[w * DOUT];
    float v0 = fmaf(a[l], sc2[l], sh2[l]);
    float v1 = (l < 8) ? fmaf(a[32 + l], sc2[32 + l], sh2[32 + l]) : -1e30f;
    float m = fmaxf(v0, v1);
#pragma unroll
    for (int o = 16; o > 0; o >>= 1) m = fmaxf(m, __shfl_xor_sync(0xffffffffu, m, o));
    float e = expf(v0 - m) + ((l < 8) ? expf(v1 - m) : 0.f);
#pragma unroll
    for (int o = 16; o > 0; o >>= 1) e += __shfl_xor_sync(0xffffffffu, e, o);
    float ls = m + logf(e);
    out[w * DOUT + l] = v0 - ls;
    if (l < 8) out[w * DOUT + 32 + l] = v1 - ls;
}

// ---------------- launch ----------------
extern "C" void kernel_launch(void* const* d_in, const int* in_sizes, int n_in,
                              void* d_out, int out_size) {
    const float* x      = (const float*)d_in[0];
    const void*  ei     = d_in[1];
    const float* W1     = (const float*)d_in[2];
    const float* W2     = (const float*)d_in[4];
    const float* gamma1 = (const float*)d_in[6];
    const float* beta1  = (const float*)d_in[7];
    const float* gamma2 = (const float*)d_in[8];
    const float* beta2  = (const float*)d_in[9];
    float* out = (float*)d_out;

    int N = in_sizes[0] / DIN;     // 50000
    int E = in_sizes[1] / 2;       // 800000
    float invN = 1.0f / (float)N;

    size_t smem1 = (size_t)(128 * AS_STRIDE + 104 * BS_STRIDE) * sizeof(float);
    size_t smem2 = (size_t)(128 * G2_AST + 256 * DOUT + 512) * sizeof(float);
    static int smem_set = 0;
    if (!smem_set) {
        cudaFuncSetAttribute(k_gemm1_tf32, cudaFuncAttributeMaxDynamicSharedMemorySize,
                             (int)smem1);
        cudaFuncSetAttribute(k_gemm2_tf32, cudaFuncAttributeMaxDynamicSharedMemorySize,
                             (int)smem2);
        smem_set = 1;
    }

    // init + CSR build
    k_init<<<200, 256>>>((const int*)ei, N);
    k_count<<<(E + 255) / 256, 256>>>(ei, E);
    k_scan<<<1, 1024>>>(N);
    k_fill<<<(E + 255) / 256, 256>>>(ei, E);

    // layer 1
    k_gather1<<<(N * 25 + 255) / 256, 256>>>(x, N);
    dim3 g1((N + 127) / 128, 2);
    k_gemm1_tf32<<<g1, 256, smem1>>>(W1, N);

    // layer 2
    k_gemm2_tf32<<<(N + 127) / 128, 256, smem2>>>(W2, gamma1, beta1, invN, N);
    k_gather2<<<G2BLOCKS, 256>>>(N);

    k_logsoftmax<<<(N + 7) / 8, 256>>>(out, gamma2, beta2, invN, N);
}